// round 13
// baseline (speedup 1.0000x reference)
#include <cuda_runtime.h>
#include <cuda_bf16.h>
#include <cstdint>

#define N_NODES 100000
#define N_EDGES 1600000
#define NFEAT   128
#define NCLASS  40
#define BN_EPS  1e-5f

// ---------------- scratch (static device globals; no allocation) ----------------
__device__ int   g_deg[N_NODES];
__device__ int   g_off[N_NODES];
__device__ int   g_cur[N_NODES];
__device__ float g_inv[N_NODES];
__device__ int   g_csr[N_EDGES];
__device__ int   g_bsums[128];
__device__ int   g_is64;

__device__ float g_mean[(size_t)N_NODES * NFEAT];
__device__ float g_h1[(size_t)N_NODES * NFEAT];
__device__ float g_h2[(size_t)N_NODES * NFEAT];

__device__ __align__(16) float g_bnsum[NFEAT];
__device__ __align__(16) float g_bnsq[NFEAT];
__device__ __align__(16) float g_bnscale[NFEAT];
__device__ __align__(16) float g_bnshift[NFEAT];

// tf32 helpers
__device__ __forceinline__ float tf32_rna(float v) {
    uint32_t u;
    asm("cvt.rna.tf32.f32 %0, %1;" : "=r"(u) : "f"(v));
    return __uint_as_float(u);
}

#define MMA_TF32(d, a, b) \
    asm("mma.sync.aligned.m16n8k8.row.col.f32.tf32.tf32.f32 " \
        "{%0,%1,%2,%3},{%4,%5,%6,%7},{%8,%9},{%0,%1,%2,%3};" \
        : "+f"(d[0]), "+f"(d[1]), "+f"(d[2]), "+f"(d[3]) \
        : "r"(a[0]), "r"(a[1]), "r"(a[2]), "r"(a[3]), "r"(b[0]), "r"(b[1]))

// ---------------- setup: dtype detect + degree zero (fused) ----------------
__global__ void setup_kernel(const int* __restrict__ ei32) {
    int i = blockIdx.x * blockDim.x + threadIdx.x;
    if (i < N_NODES) g_deg[i] = 0;
    // int64 => every odd int32 word (high word) is 0 (all ids < 1e5).
    if (blockIdx.x == 0) {
        __shared__ int any;
        if (threadIdx.x == 0) any = 0;
        __syncthreads();
        int nz = 0;
        for (int t = threadIdx.x; t < 1024; t += blockDim.x)
            if (ei32[2 * t + 1] != 0) nz = 1;
        if (nz) atomicOr(&any, 1);
        __syncthreads();
        if (threadIdx.x == 0) g_is64 = any ? 0 : 1;
    }
}

__device__ __forceinline__ int edge_elem(const int* __restrict__ ei32, int idx) {
    return g_is64 ? ei32[2 * idx] : ei32[idx];
}

// ---------------- CSR build ----------------
__global__ void hist_kernel(const int* __restrict__ ei32) {
    int e = blockIdx.x * blockDim.x + threadIdx.x;
    if (e < N_EDGES) {
        int d = edge_elem(ei32, N_EDGES + e);
        atomicAdd(&g_deg[d], 1);
    }
}

__global__ void scan1_kernel() {
    __shared__ int s[1024];
    int i = blockIdx.x * 1024 + threadIdx.x;
    int v = (i < N_NODES) ? g_deg[i] : 0;
    s[threadIdx.x] = v;
    __syncthreads();
    for (int off = 1; off < 1024; off <<= 1) {
        int t = (threadIdx.x >= off) ? s[threadIdx.x - off] : 0;
        __syncthreads();
        s[threadIdx.x] += t;
        __syncthreads();
    }
    if (i < N_NODES) g_off[i] = s[threadIdx.x] - v;
    if (threadIdx.x == 1023) g_bsums[blockIdx.x] = s[1023];
}

__global__ void scan23_kernel(int nblocks) {
    __shared__ int s[256];
    int t = threadIdx.x;
    int v = (t < nblocks) ? g_bsums[t] : 0;
    s[t] = v;
    __syncthreads();
    for (int off = 1; off < 256; off <<= 1) {
        int u = (t >= off) ? s[t - off] : 0;
        __syncthreads();
        s[t] += u;
        __syncthreads();
    }
    __shared__ int excl[256];
    excl[t] = s[t] - v;
    __syncthreads();

    int i = blockIdx.x * blockDim.x + t;
    if (i < N_NODES) {
        int o = g_off[i] + excl[i >> 10];
        g_off[i] = o;
        g_cur[i] = o;
        int d = g_deg[i];
        g_inv[i] = 1.0f / (float)(d > 1 ? d : 1);
    }
}

__global__ void scatter_kernel(const int* __restrict__ ei32) {
    int e = blockIdx.x * blockDim.x + threadIdx.x;
    if (e < N_EDGES) {
        int s = edge_elem(ei32, e);
        int d = edge_elem(ei32, N_EDGES + e);
        int p = atomicAdd(&g_cur[d], 1);
        g_csr[p] = s;
    }
}

// ---------------- aggregation: warp per node, float4 lanes ----------------
__global__ void agg_kernel(const float* __restrict__ X, float* __restrict__ out) {
    int warp = (blockIdx.x * blockDim.x + threadIdx.x) >> 5;
    if (warp >= N_NODES) return;
    int lane = threadIdx.x & 31;
    int beg = g_off[warp];
    int cnt = g_deg[warp];
    const float4* __restrict__ Xv = (const float4*)X;

    float4 a0 = make_float4(0.f, 0.f, 0.f, 0.f);
    float4 a1 = a0, a2 = a0, a3 = a0;

    int i = 0;
    for (; i + 4 <= cnt; i += 4) {
        int s0 = g_csr[beg + i + 0];
        int s1 = g_csr[beg + i + 1];
        int s2 = g_csr[beg + i + 2];
        int s3 = g_csr[beg + i + 3];
        float4 v0 = Xv[s0 * 32 + lane];
        float4 v1 = Xv[s1 * 32 + lane];
        float4 v2 = Xv[s2 * 32 + lane];
        float4 v3 = Xv[s3 * 32 + lane];
        a0.x += v0.x; a0.y += v0.y; a0.z += v0.z; a0.w += v0.w;
        a1.x += v1.x; a1.y += v1.y; a1.z += v1.z; a1.w += v1.w;
        a2.x += v2.x; a2.y += v2.y; a2.z += v2.z; a2.w += v2.w;
        a3.x += v3.x; a3.y += v3.y; a3.z += v3.z; a3.w += v3.w;
    }
    for (; i < cnt; i++) {
        int s0 = g_csr[beg + i];
        float4 v0 = Xv[s0 * 32 + lane];
        a0.x += v0.x; a0.y += v0.y; a0.z += v0.z; a0.w += v0.w;
    }
    float inv = g_inv[warp];
    float4 r;
    r.x = (a0.x + a1.x + a2.x + a3.x) * inv;
    r.y = (a0.y + a1.y + a2.y + a3.y) * inv;
    r.z = (a0.z + a1.z + a2.z + a3.z) * inv;
    r.w = (a0.w + a1.w + a2.w + a3.w) * inv;
    ((float4*)out)[warp * 32 + lane] = r;
}

// agg over y = relu(bn(X)) applied on the fly.
__global__ void agg_bn_kernel(const float* __restrict__ X, float* __restrict__ out) {
    int warp = (blockIdx.x * blockDim.x + threadIdx.x) >> 5;
    if (warp >= N_NODES) return;
    int lane = threadIdx.x & 31;
    int beg = g_off[warp];
    int cnt = g_deg[warp];
    const float4* __restrict__ Xv = (const float4*)X;

    float4 sc = *(const float4*)&g_bnscale[lane * 4];
    float4 sh = *(const float4*)&g_bnshift[lane * 4];

    float4 a0 = make_float4(0.f, 0.f, 0.f, 0.f);
    float4 a1 = a0;

    int i = 0;
    for (; i + 2 <= cnt; i += 2) {
        int s0 = g_csr[beg + i + 0];
        int s1 = g_csr[beg + i + 1];
        float4 v0 = Xv[s0 * 32 + lane];
        float4 v1 = Xv[s1 * 32 + lane];
        a0.x += fmaxf(fmaf(v0.x, sc.x, sh.x), 0.f);
        a0.y += fmaxf(fmaf(v0.y, sc.y, sh.y), 0.f);
        a0.z += fmaxf(fmaf(v0.z, sc.z, sh.z), 0.f);
        a0.w += fmaxf(fmaf(v0.w, sc.w, sh.w), 0.f);
        a1.x += fmaxf(fmaf(v1.x, sc.x, sh.x), 0.f);
        a1.y += fmaxf(fmaf(v1.y, sc.y, sh.y), 0.f);
        a1.z += fmaxf(fmaf(v1.z, sc.z, sh.z), 0.f);
        a1.w += fmaxf(fmaf(v1.w, sc.w, sh.w), 0.f);
    }
    for (; i < cnt; i++) {
        int s0 = g_csr[beg + i];
        float4 v0 = Xv[s0 * 32 + lane];
        a0.x += fmaxf(fmaf(v0.x, sc.x, sh.x), 0.f);
        a0.y += fmaxf(fmaf(v0.y, sc.y, sh.y), 0.f);
        a0.z += fmaxf(fmaf(v0.z, sc.z, sh.z), 0.f);
        a0.w += fmaxf(fmaf(v0.w, sc.w, sh.w), 0.f);
    }
    float inv = g_inv[warp];
    float4 r;
    r.x = (a0.x + a1.x) * inv;
    r.y = (a0.y + a1.y) * inv;
    r.z = (a0.z + a1.z) * inv;
    r.w = (a0.w + a1.w) * inv;
    ((float4*)out)[warp * 32 + lane] = r;
}

// ---------------- 3xTF32 tensor-core GEMM: out (+)= A@W^T [+bias] [relu] ----------
// BM=128, BN=128, BK=16, 256 threads (8 warps as 4m x 2n), warp tile 32x64,
// mma.sync.m16n8k8.tf32 with 3xTF32 error compensation (hi*hi + hi*lo + lo*hi).
// ZERO_BN: block 0 additionally zeroes the BN accumulators for the next stats pass.
template <bool ACCUM, bool RELU, bool ZERO_BN>
__global__ void __launch_bounds__(256)
gemm128_tf32_kernel(const float* __restrict__ A, const float* __restrict__ W,
                    const float* __restrict__ bias, float* __restrict__ out) {
    __shared__ float As_hi[16][132], As_lo[16][132];
    __shared__ float Bs_hi[16][132], Bs_lo[16][132];

    int tid  = threadIdx.x;
    int lane = tid & 31, wid = tid >> 5;
    int gid  = lane >> 2, tig = lane & 3;          // mma fragment coords
    int wm   = (wid & 3) * 32, wn = (wid >> 2) * 64;
    int rowBase = blockIdx.x * 128;
    int lrow = tid >> 1;            // 0..127
    int lk   = (tid & 1) * 8;       // 0 or 8

    if (ZERO_BN && blockIdx.x == 0 && tid < NFEAT) { g_bnsum[tid] = 0.f; g_bnsq[tid] = 0.f; }

    float acc[2][8][4];
#pragma unroll
    for (int mt = 0; mt < 2; mt++)
#pragma unroll
        for (int nt = 0; nt < 8; nt++)
#pragma unroll
            for (int r = 0; r < 4; r++) acc[mt][nt][r] = 0.f;

    for (int c = 0; c < 8; c++) {
        int ko = c * 16;

        // stage global -> regs
        float av[8], wv[8];
        {
            int g = rowBase + lrow;
            if (g < N_NODES) {
                const float4* p = (const float4*)(A + (size_t)g * 128 + ko + lk);
                float4 a0 = p[0], a1 = p[1];
                av[0] = a0.x; av[1] = a0.y; av[2] = a0.z; av[3] = a0.w;
                av[4] = a1.x; av[5] = a1.y; av[6] = a1.z; av[7] = a1.w;
            } else {
#pragma unroll
                for (int j = 0; j < 8; j++) av[j] = 0.f;
            }
            const float4* q = (const float4*)(W + lrow * 128 + ko + lk);
            float4 b0 = q[0], b1 = q[1];
            wv[0] = b0.x; wv[1] = b0.y; wv[2] = b0.z; wv[3] = b0.w;
            wv[4] = b1.x; wv[5] = b1.y; wv[6] = b1.z; wv[7] = b1.w;
        }

        __syncthreads();
#pragma unroll
        for (int j = 0; j < 8; j++) {
            float hi = tf32_rna(av[j]);
            As_hi[lk + j][lrow] = hi;
            As_lo[lk + j][lrow] = tf32_rna(av[j] - hi);
            float whi = tf32_rna(wv[j]);
            Bs_hi[lk + j][lrow] = whi;
            Bs_lo[lk + j][lrow] = tf32_rna(wv[j] - whi);
        }
        __syncthreads();

#pragma unroll
        for (int s = 0; s < 16; s += 8) {
            uint32_t ah[2][4], al[2][4];
#pragma unroll
            for (int mt = 0; mt < 2; mt++) {
                int m0 = wm + mt * 16;
                ah[mt][0] = __float_as_uint(As_hi[s + tig    ][m0 + gid    ]);
                ah[mt][1] = __float_as_uint(As_hi[s + tig    ][m0 + gid + 8]);
                ah[mt][2] = __float_as_uint(As_hi[s + tig + 4][m0 + gid    ]);
                ah[mt][3] = __float_as_uint(As_hi[s + tig + 4][m0 + gid + 8]);
                al[mt][0] = __float_as_uint(As_lo[s + tig    ][m0 + gid    ]);
                al[mt][1] = __float_as_uint(As_lo[s + tig    ][m0 + gid + 8]);
                al[mt][2] = __float_as_uint(As_lo[s + tig + 4][m0 + gid    ]);
                al[mt][3] = __float_as_uint(As_lo[s + tig + 4][m0 + gid + 8]);
            }
#pragma unroll
            for (int nt = 0; nt < 8; nt++) {
                int n0 = wn + nt * 8;
                uint32_t bh[2], bl[2];
                bh[0] = __float_as_uint(Bs_hi[s + tig    ][n0 + gid]);
                bh[1] = __float_as_uint(Bs_hi[s + tig + 4][n0 + gid]);
                bl[0] = __float_as_uint(Bs_lo[s + tig    ][n0 + gid]);
                bl[1] = __float_as_uint(Bs_lo[s + tig + 4][n0 + gid]);
#pragma unroll
                for (int mt = 0; mt < 2; mt++) {
                    MMA_TF32(acc[mt][nt], ah[mt], bh);
                    MMA_TF32(acc[mt][nt], ah[mt], bl);
                    MMA_TF32(acc[mt][nt], al[mt], bh);
                }
            }
        }
    }

    // epilogue
#pragma unroll
    for (int mt = 0; mt < 2; mt++) {
        int r0 = rowBase + wm + mt * 16 + gid;
#pragma unroll
        for (int nt = 0; nt < 8; nt++) {
            int col = wn + nt * 8 + tig * 2;
            float2 bv;
            if (!ACCUM) { bv.x = __ldg(&bias[col]); bv.y = __ldg(&bias[col + 1]); }

            if (r0 < N_NODES) {
                float2 v;
                if (ACCUM) {
                    float2 o = *(float2*)(out + (size_t)r0 * 128 + col);
                    v.x = acc[mt][nt][0] + o.x; v.y = acc[mt][nt][1] + o.y;
                } else {
                    v.x = acc[mt][nt][0] + bv.x; v.y = acc[mt][nt][1] + bv.y;
                }
                if (RELU) { v.x = fmaxf(v.x, 0.f); v.y = fmaxf(v.y, 0.f); }
                *(float2*)(out + (size_t)r0 * 128 + col) = v;
            }
            int r1 = r0 + 8;
            if (r1 < N_NODES) {
                float2 v;
                if (ACCUM) {
                    float2 o = *(float2*)(out + (size_t)r1 * 128 + col);
                    v.x = acc[mt][nt][2] + o.x; v.y = acc[mt][nt][3] + o.y;
                } else {
                    v.x = acc[mt][nt][2] + bv.x; v.y = acc[mt][nt][3] + bv.y;
                }
                if (RELU) { v.x = fmaxf(v.x, 0.f); v.y = fmaxf(v.y, 0.f); }
                *(float2*)(out + (size_t)r1 * 128 + col) = v;
            }
        }
    }
}

// ---------------- gemm40: out = mean@W2l^T + b2 + relu(bn(h2))@W2r^T ----------------
__global__ void gemm40_kernel(const float* __restrict__ Am, const float* __restrict__ Ax,
                              const float* __restrict__ Wl, const float* __restrict__ Wr,
                              const float* __restrict__ bias, float* __restrict__ out) {
    __shared__ float As[32][65];
    __shared__ float Bs[40][33];

    int tid = threadIdx.x;
    int tx = tid & 7;
    int ty = tid >> 3;
    int rowBase = blockIdx.x * 64;

    if (blockIdx.x == 0 && tid < NFEAT) { g_bnsum[tid] = 0.f; g_bnsq[tid] = 0.f; }

    float acc[4][5];
#pragma unroll
    for (int i = 0; i < 4; i++)
#pragma unroll
        for (int j = 0; j < 5; j++) acc[i][j] = 0.f;

    for (int c = 0; c < 8; c++) {
        bool isL = (c < 4);
        const float* A = isL ? Am : Ax;
        const float* W = isL ? Wl : Wr;
        int ko = (c & 3) * 32;

#pragma unroll
        for (int p = 0; p < 16; p++) {
            int idx = tid + p * 128;
            int row = idx >> 5, kk = idx & 31;
            int g = rowBase + row;
            float v = 0.f;
            if (g < N_NODES) {
                v = A[(size_t)g * 128 + ko + kk];
                if (!isL) v = fmaxf(fmaf(v, g_bnscale[ko + kk], g_bnshift[ko + kk]), 0.f);
            }
            As[kk][row] = v;
        }
#pragma unroll
        for (int p = 0; p < 10; p++) {
            int idx = tid + p * 128;
            if (idx < 40 * 32) {
                int o = idx >> 5, kk = idx & 31;
                Bs[o][kk] = W[o * 128 + ko + kk];
            }
        }
        __syncthreads();

#pragma unroll
        for (int kk = 0; kk < 32; kk++) {
            float a[4], b[5];
#pragma unroll
            for (int i = 0; i < 4; i++) a[i] = As[kk][ty + 16 * i];
#pragma unroll
            for (int j = 0; j < 5; j++) b[j] = Bs[tx + 8 * j][kk];
#pragma unroll
            for (int i = 0; i < 4; i++)
#pragma unroll
                for (int j = 0; j < 5; j++) acc[i][j] += a[i] * b[j];
        }
        __syncthreads();
    }

#pragma unroll
    for (int i = 0; i < 4; i++) {
        int g = rowBase + ty + 16 * i;
        if (g < N_NODES) {
#pragma unroll
            for (int j = 0; j < 5; j++) {
                int o = tx + 8 * j;
                out[(size_t)g * 40 + o] = acc[i][j] + __ldg(&bias[o]);
            }
        }
    }
}

// ---------------- batch norm ----------------
template <int F>
__global__ void bn_stats_kernel(const float* __restrict__ X, int rowsPerBlock) {
    int c4 = threadIdx.x;
    if (c4 >= F / 4) return;
    int r0 = blockIdx.x * rowsPerBlock;
    int r1 = r0 + rowsPerBlock;
    if (r1 > N_NODES) r1 = N_NODES;
    const float4* Xv = (const float4*)X;
    float4 s = make_float4(0.f, 0.f, 0.f, 0.f);
    float4 q = make_float4(0.f, 0.f, 0.f, 0.f);
    for (int r = r0; r < r1; r++) {
        float4 v = Xv[(size_t)r * (F / 4) + c4];
        s.x += v.x; s.y += v.y; s.z += v.z; s.w += v.w;
        q.x += v.x * v.x; q.y += v.y * v.y; q.z += v.z * v.z; q.w += v.w * v.w;
    }
    atomicAdd(&g_bnsum[c4 * 4 + 0], s.x);
    atomicAdd(&g_bnsum[c4 * 4 + 1], s.y);
    atomicAdd(&g_bnsum[c4 * 4 + 2], s.z);
    atomicAdd(&g_bnsum[c4 * 4 + 3], s.w);
    atomicAdd(&g_bnsq[c4 * 4 + 0], q.x);
    atomicAdd(&g_bnsq[c4 * 4 + 1], q.y);
    atomicAdd(&g_bnsq[c4 * 4 + 2], q.z);
    atomicAdd(&g_bnsq[c4 * 4 + 3], q.w);
}

template <int F>
__global__ void bn_final_kernel(const float* __restrict__ gamma, const float* __restrict__ beta) {
    int c = threadIdx.x;
    if (c >= F) return;
    float invN = 1.0f / (float)N_NODES;
    float mu = g_bnsum[c] * invN;
    float var = g_bnsq[c] * invN - mu * mu;
    var = fmaxf(var, 0.f);
    float sc = gamma[c] * rsqrtf(var + BN_EPS);
    g_bnscale[c] = sc;
    g_bnshift[c] = beta[c] - mu * sc;
}

template <int F, bool RELU>
__global__ void bn_apply_kernel(float* __restrict__ X) {
    long long i = (long long)blockIdx.x * blockDim.x + threadIdx.x;
    long long total = (long long)N_NODES * F;
    if (i < total) {
        int col = (int)(i % F);
        float v = X[i] * g_bnscale[col] + g_bnshift[col];
        if (RELU) v = fmaxf(v, 0.f);
        X[i] = v;
    }
}

// ---------------- launch ----------------
extern "C" void kernel_launch(void* const* d_in, const int* in_sizes, int n_in,
                              void* d_out, int out_size) {
    const float* x    = (const float*)d_in[0];
    const int*   ei32 = (const int*)  d_in[1];
    const float* W1l = (const float*)d_in[2];
    const float* b1  = (const float*)d_in[3];
    const float* W1r = (const float*)d_in[4];
    const float* Wxl = (const float*)d_in[5];
    const float* bx  = (const float*)d_in[6];
    const float* Wxr = (const float*)d_in[7];
    const float* W2l = (const float*)d_in[8];
    const float* b2  = (const float*)d_in[9];
    const float* W2r = (const float*)d_in[10];
    const float* g3  = (const float*)d_in[11];
    const float* be3 = (const float*)d_in[12];
    const float* g2  = (const float*)d_in[13];
    const float* be2 = (const float*)d_in[14];
    float* out = (float*)d_out;

    float* mean = nullptr; float* h1 = nullptr; float* h2 = nullptr;
    cudaGetSymbolAddress((void**)&mean, g_mean);
    cudaGetSymbolAddress((void**)&h1, g_h1);
    cudaGetSymbolAddress((void**)&h2, g_h2);

    const int NB_NODE = (N_NODES + 255) / 256;       // 391
    const int NB_EDGE = (N_EDGES + 255) / 256;       // 6250
    const int NB_SCAN = (N_NODES + 1023) / 1024;     // 98
    const int NB_AGG  = (N_NODES + 15) / 16;         // warp/node, 16 warps/block
    const int NB_G128 = (N_NODES + 127) / 128;       // 782
    const int NB_G40  = (N_NODES + 63) / 64;         // 1563
    const int BN_BLOCKS = 256;
    const int ROWS_PER_BLOCK = (N_NODES + BN_BLOCKS - 1) / BN_BLOCKS;

    // 1-3: CSR build phase A
    setup_kernel<<<NB_NODE, 256>>>(ei32);
    hist_kernel<<<NB_EDGE, 256>>>(ei32);
    scan1_kernel<<<NB_SCAN, 1024>>>();

    // 4: conv1 root term (CSR-independent): h1 = x@W1r^T + b1.  PROFILED (#4).
    gemm128_tf32_kernel<false, false, false><<<NB_G128, 256>>>(x, W1r, b1, h1);

    // 5-6: CSR build phase B
    scan23_kernel<<<NB_NODE, 256>>>(NB_SCAN);
    scatter_kernel<<<NB_EDGE, 256>>>(ei32);

    // 7-8: conv1 neighbor term + relu: h1 = relu(h1 + mean@W1l^T)
    agg_kernel<<<NB_AGG, 512>>>(x, mean);
    gemm128_tf32_kernel<true, true, false><<<NB_G128, 256>>>(mean, W1l, b1, h1);

    // 9-11: convx: h2 = mean@Wxl^T + bx + h1@Wxr^T (bn3 accums zeroed in #11)
    agg_kernel<<<NB_AGG, 512>>>(h1, mean);
    gemm128_tf32_kernel<false, false, false><<<NB_G128, 256>>>(mean, Wxl, bx, h2);
    gemm128_tf32_kernel<true, false, true><<<NB_G128, 256>>>(h1, Wxr, bx, h2);

    // 12-13: bn3 stats on raw h2; scale/shift computed (application fused downstream)
    bn_stats_kernel<128><<<BN_BLOCKS, 32>>>(h2, ROWS_PER_BLOCK);
    bn_final_kernel<128><<<1, 128>>>(g3, be3);

    // 14-15: conv2 — agg over relu(bn(h2)); gemm40 stages Ax with bn+relu inline;
    //         bn2 accums zeroed inside gemm40
    agg_bn_kernel<<<NB_AGG, 512>>>(h2, mean);
    gemm40_kernel<<<NB_G40, 128>>>(mean, h2, W2l, W2r, b2, out);

    // 16-18: bn2 on out
    bn_stats_kernel<40><<<BN_BLOCKS, 16>>>(out, ROWS_PER_BLOCK);
    bn_final_kernel<40><<<1, 64>>>(g2, be2);
    {
        long long total = (long long)N_NODES * 40;
        int nb = (int)((total + 255) / 256);
        bn_apply_kernel<40, false><<<nb, 256>>>(out);
    }
}